// round 5
// baseline (speedup 1.0000x reference)
#include <cuda_runtime.h>
#include <math.h>

#define W_ 256
#define H_ 256
#define NMAX 768
#define NWORDS 24               // ceil(768/32)
#define NTILES 1024             // 32x32 tiles of 8x8 px
#define CUT_SIGMA 5.5412636f    // log(255): alpha >= 1/255  <=>  sigma <= log(255)

// depth-sorted gaussian data (written at rank)
__device__ float4 g_A[NMAX];    // mx, my, 0.5*conicA, 0.5*conicC
__device__ float4 g_B[NMAX];    // conicB, bias(=-log op), r, g
__device__ float  g_bv[NMAX];   // blue
__device__ float4 g_bb[NMAX];   // x0, x1, y0, y1
__device__ unsigned g_mask[NTILES][NWORDS];   // per-tile candidate bitmask (bit = sorted rank)

__global__ __launch_bounds__(256) void gs_prep_sort(
        const float* __restrict__ means,
        const float* __restrict__ quats,
        const float* __restrict__ scales,
        const float* __restrict__ opac_in,
        const float* __restrict__ rgbs,
        int n) {
    __shared__ float sz[NMAX];
    int tid = threadIdx.x;
    int i = blockIdx.x * blockDim.x + tid;

    for (int j = tid; j < n; j += 256)
        sz[j] = means[j*3+2];
    __syncthreads();

    if (i >= n) return;

    float zi = sz[i];
    int rank = 0;
    #pragma unroll 8
    for (int j = 0; j < n; j++) {
        float zj = sz[j];
        rank += (zj < zi || (zj == zi && j < i)) ? 1 : 0;
    }

    float qw = quats[i*4+0], qx = quats[i*4+1], qy = quats[i*4+2], qz = quats[i*4+3];
    float inv = rsqrtf(qw*qw + qx*qx + qy*qy + qz*qz);
    float w = qw*inv, x = qx*inv, y = qy*inv, z = qz*inv;

    float R00 = 1.f - 2.f*(y*y + z*z), R01 = 2.f*(x*y - w*z), R02 = 2.f*(x*z + w*y);
    float R10 = 2.f*(x*y + w*z), R11 = 1.f - 2.f*(x*x + z*z), R12 = 2.f*(y*z - w*x);
    float R20 = 2.f*(x*z - w*y), R21 = 2.f*(y*z + w*x), R22 = 1.f - 2.f*(x*x + y*y);

    float sx = scales[i*3+0], sy = scales[i*3+1], szc = scales[i*3+2];
    float s0 = sx*sx, s1 = sy*sy, s2 = szc*szc;

    float C00 = R00*R00*s0 + R01*R01*s1 + R02*R02*s2;
    float C01 = R00*R10*s0 + R01*R11*s1 + R02*R12*s2;
    float C02 = R00*R20*s0 + R01*R21*s1 + R02*R22*s2;
    float C11 = R10*R10*s0 + R11*R11*s1 + R12*R12*s2;
    float C12 = R10*R20*s0 + R11*R21*s1 + R12*R22*s2;
    float C22 = R20*R20*s0 + R21*R21*s1 + R22*R22*s2;

    float tx = means[i*3+0], ty = means[i*3+1], tz = zi + 8.0f;
    const float f = 128.0f;
    float iz = 1.0f / tz;
    float j00 = f * iz;
    float j02 = -f * tx * iz * iz;
    float j12 = -f * ty * iz * iz;

    float a = j00*j00*C00 + 2.f*j00*j02*C02 + j02*j02*C22 + 0.3f;
    float b = j00*j00*C01 + j00*j12*C02 + j02*j00*C12 + j02*j12*C22;
    float c = j00*j00*C11 + 2.f*j00*j12*C12 + j12*j12*C22 + 0.3f;

    float det = a*c - b*b;
    float idet = 1.0f / det;
    float cA = c * idet, cB = -b * idet, cC = a * idet;

    float mx = f * tx * iz + 128.0f;
    float my = f * ty * iz + 128.0f;

    float op = 1.0f / (1.0f + __expf(-opac_in[i]));
    float cr = 1.0f / (1.0f + __expf(-rgbs[i*3+0]));
    float cg = 1.0f / (1.0f + __expf(-rgbs[i*3+1]));
    float cb = 1.0f / (1.0f + __expf(-rgbs[i*3+2]));

    float bias = -__logf(op);
    float tcut = CUT_SIGMA - bias;
    float ex, ey;
    if (tcut > 0.0f) {
        ex = sqrtf(2.0f * tcut * a) + 0.5f;
        ey = sqrtf(2.0f * tcut * c) + 0.5f;
    } else {
        ex = -1e30f; ey = -1e30f;
    }

    g_A[rank]  = make_float4(mx, my, 0.5f * cA, 0.5f * cC);
    g_B[rank]  = make_float4(cB, bias, cr, cg);
    g_bv[rank] = cb;
    g_bb[rank] = make_float4(mx - ex, mx + ex, my - ey, my + ey);
}

// One warp per 8x8 tile: build the candidate bitmask (bit index = sorted rank).
__global__ __launch_bounds__(256) void gs_bin(int n) {
    int warp = (blockIdx.x * 256 + threadIdx.x) >> 5;
    int lane = threadIdx.x & 31;
    if (warp >= NTILES) return;
    int tx = warp & 31, ty = warp >> 5;
    const float tlx = tx * 8 + 0.5f, thx = tx * 8 + 7.5f;
    const float tly = ty * 8 + 0.5f, thy = ty * 8 + 7.5f;

    #pragma unroll
    for (int w = 0; w < NWORDS; w++) {
        int g = w * 32 + lane;
        bool pred = false;
        if (g < n) {
            float4 bb = g_bb[g];
            pred = (bb.y >= tlx) & (bb.x <= thx) & (bb.w >= tly) & (bb.z <= thy);
        }
        unsigned m = __ballot_sync(0xffffffffu, pred);
        if (lane == 0) g_mask[warp][w] = m;
    }
}

// 8x8 tile per block, 64 threads, 1 px/thread.
__global__ __launch_bounds__(64) void gs_render(float* __restrict__ out, int n) {
    __shared__ float4 sA[NMAX];
    __shared__ float4 sB[NMAX];
    __shared__ float  sBV[NMAX];
    __shared__ unsigned short s_idx[NMAX];
    __shared__ int s_cnt;

    const int tid = threadIdx.x;
    const int tile = blockIdx.y * 32 + blockIdx.x;
    const int px0 = blockIdx.x * 8, py0 = blockIdx.y * 8;

    // warp 0: expand bitmask into ordered candidate index list
    if (tid < 32) {
        unsigned word = (tid < NWORDS) ? g_mask[tile][tid] : 0u;
        int c = __popc(word);
        int sc = c;
        #pragma unroll
        for (int o = 1; o < 32; o <<= 1) {
            int v = __shfl_up_sync(0xffffffffu, sc, o);
            if (tid >= o) sc += v;
        }
        if (tid == 31) s_cnt = sc;
        int off = sc - c;
        int base = tid * 32;
        while (word) {
            int b = __ffs(word) - 1;
            s_idx[off++] = (unsigned short)(base + b);
            word &= word - 1;
        }
    }
    __syncthreads();
    const int cnt = s_cnt;

    // stage candidates into shared
    for (int k = tid; k < cnt; k += 64) {
        int g = s_idx[k];
        sA[k]  = g_A[g];
        sB[k]  = g_B[g];
        sBV[k] = g_bv[g];
    }
    __syncthreads();

    const float pxc = px0 + (tid & 7) + 0.5f;
    const float pyc = py0 + (tid >> 3) + 0.5f;

    float T = 1.0f, ar = 0.0f, ag = 0.0f, ab = 0.0f;
    #pragma unroll 4
    for (int k = 0; k < cnt; k++) {
        float4 A = sA[k];
        float dx = pxc - A.x;
        float dy = pyc - A.y;
        float4 B = sB[k];
        float sigma = fmaf(A.z, dx*dx, fmaf(A.w, dy*dy, fmaf(B.x, dx*dy, B.y)));
        if (sigma <= CUT_SIGMA) {
            float al = fminf(0.999f, __expf(-sigma));
            float wt = T * al;
            ar = fmaf(wt, B.z, ar);
            ag = fmaf(wt, B.w, ag);
            ab = fmaf(wt, sBV[k], ab);
            T -= wt;
            if (T < 2e-6f) break;
        }
    }

    int p = (py0 + (tid >> 3)) * W_ + (px0 + (tid & 7));
    out[3*p + 0] = ar;
    out[3*p + 1] = ag;
    out[3*p + 2] = ab;
}

extern "C" void kernel_launch(void* const* d_in, const int* in_sizes, int n_in,
                              void* d_out, int out_size) {
    const float* means  = (const float*)d_in[1];
    const float* quats  = (const float*)d_in[2];
    const float* scales = (const float*)d_in[3];
    const float* opac   = (const float*)d_in[4];
    const float* rgbs   = (const float*)d_in[5];
    int n = in_sizes[4];
    if (n > NMAX) n = NMAX;

    gs_prep_sort<<<(n + 255) / 256, 256>>>(means, quats, scales, opac, rgbs, n);
    gs_bin<<<(NTILES * 32 + 255) / 256, 256>>>(n);
    dim3 grid(W_ / 8, H_ / 8), block(64);
    gs_render<<<grid, block>>>((float*)d_out, n);
}

// round 6
// speedup vs baseline: 1.2796x; 1.2796x over previous
#include <cuda_runtime.h>
#include <math.h>

#define W_ 256
#define H_ 256
#define NMAX 768
#define NWORDS 24               // ceil(768/32)
#define NTILES 1024             // 32x32 tiles of 8x8 px
#define CUT_SIGMA 5.5412636f    // log(255): alpha >= 1/255  <=>  sigma <= log(255)

// depth-sorted gaussian data (written at rank)
__device__ float4 g_A[NMAX];    // mx, my, 0.5*conicA, 0.5*conicC
__device__ float4 g_B[NMAX];    // conicB, bias(=-log op), r, g
__device__ float  g_bv[NMAX];   // blue
__device__ float4 g_bb[NMAX];   // x0, x1, y0, y1
__device__ unsigned g_mask[NTILES][NWORDS];   // per-tile candidate bitmask (bit = sorted rank)

// Fused preprocess + stable rank sort. ONE WARP PER GAUSSIAN:
// lanes split the O(N) rank scan, then all lanes run the projection math
// redundantly (SIMT-free), lane 0 scatters to the rank slot.
__global__ __launch_bounds__(256) void gs_prep_sort(
        const float* __restrict__ means,
        const float* __restrict__ quats,
        const float* __restrict__ scales,
        const float* __restrict__ opac_in,
        const float* __restrict__ rgbs,
        int n) {
    const int gw = (blockIdx.x * 256 + threadIdx.x) >> 5;   // gaussian index
    const int lane = threadIdx.x & 31;
    if (gw >= n) return;

    // ---- stable ascending rank by z (tz = z + 8 monotone) ----
    float zi = __ldg(&means[gw*3+2]);
    int rank = 0;
    for (int j = lane; j < n; j += 32) {
        float zj = __ldg(&means[j*3+2]);
        rank += (zj < zi || (zj == zi && j < gw)) ? 1 : 0;
    }
    #pragma unroll
    for (int o = 16; o > 0; o >>= 1)
        rank += __shfl_down_sync(0xffffffffu, rank, o);
    rank = __shfl_sync(0xffffffffu, rank, 0);

    // ---- projection (all lanes compute identically; broadcast loads) ----
    const int i = gw;
    float qw = __ldg(&quats[i*4+0]), qx = __ldg(&quats[i*4+1]);
    float qy = __ldg(&quats[i*4+2]), qz = __ldg(&quats[i*4+3]);
    float inv = rsqrtf(qw*qw + qx*qx + qy*qy + qz*qz);
    float w = qw*inv, x = qx*inv, y = qy*inv, z = qz*inv;

    float R00 = 1.f - 2.f*(y*y + z*z), R01 = 2.f*(x*y - w*z), R02 = 2.f*(x*z + w*y);
    float R10 = 2.f*(x*y + w*z), R11 = 1.f - 2.f*(x*x + z*z), R12 = 2.f*(y*z - w*x);
    float R20 = 2.f*(x*z - w*y), R21 = 2.f*(y*z + w*x), R22 = 1.f - 2.f*(x*x + y*y);

    float sx = __ldg(&scales[i*3+0]), sy = __ldg(&scales[i*3+1]), szc = __ldg(&scales[i*3+2]);
    float s0 = sx*sx, s1 = sy*sy, s2 = szc*szc;

    float C00 = R00*R00*s0 + R01*R01*s1 + R02*R02*s2;
    float C01 = R00*R10*s0 + R01*R11*s1 + R02*R12*s2;
    float C02 = R00*R20*s0 + R01*R21*s1 + R02*R22*s2;
    float C11 = R10*R10*s0 + R11*R11*s1 + R12*R12*s2;
    float C12 = R10*R20*s0 + R11*R21*s1 + R12*R22*s2;
    float C22 = R20*R20*s0 + R21*R21*s1 + R22*R22*s2;

    float tx = __ldg(&means[i*3+0]), ty = __ldg(&means[i*3+1]), tz = zi + 8.0f;
    const float f = 128.0f;
    float iz = 1.0f / tz;
    float j00 = f * iz;
    float j02 = -f * tx * iz * iz;
    float j12 = -f * ty * iz * iz;

    float a = j00*j00*C00 + 2.f*j00*j02*C02 + j02*j02*C22 + 0.3f;
    float b = j00*j00*C01 + j00*j12*C02 + j02*j00*C12 + j02*j12*C22;
    float c = j00*j00*C11 + 2.f*j00*j12*C12 + j12*j12*C22 + 0.3f;

    float det = a*c - b*b;
    float idet = 1.0f / det;
    float cA = c * idet, cB = -b * idet, cC = a * idet;

    float mx = f * tx * iz + 128.0f;
    float my = f * ty * iz + 128.0f;

    float op = 1.0f / (1.0f + __expf(-__ldg(&opac_in[i])));
    float cr = 1.0f / (1.0f + __expf(-__ldg(&rgbs[i*3+0])));
    float cg = 1.0f / (1.0f + __expf(-__ldg(&rgbs[i*3+1])));
    float cb = 1.0f / (1.0f + __expf(-__ldg(&rgbs[i*3+2])));

    float bias = -__logf(op);
    float tcut = CUT_SIGMA - bias;
    float ex, ey;
    if (tcut > 0.0f) {
        ex = sqrtf(2.0f * tcut * a) + 0.5f;
        ey = sqrtf(2.0f * tcut * c) + 0.5f;
    } else {
        ex = -1e30f; ey = -1e30f;
    }

    if (lane == 0) {
        g_A[rank]  = make_float4(mx, my, 0.5f * cA, 0.5f * cC);
        g_B[rank]  = make_float4(cB, bias, cr, cg);
        g_bv[rank] = cb;
        g_bb[rank] = make_float4(mx - ex, mx + ex, my - ey, my + ey);
    }
}

// One warp per 8x8 tile: candidate bitmask, bit index = sorted rank.
__global__ __launch_bounds__(256) void gs_bin(int n) {
    int warp = (blockIdx.x * 256 + threadIdx.x) >> 5;
    int lane = threadIdx.x & 31;
    if (warp >= NTILES) return;
    int tx = warp & 31, ty = warp >> 5;
    const float tlx = tx * 8 + 0.5f, thx = tx * 8 + 7.5f;
    const float tly = ty * 8 + 0.5f, thy = ty * 8 + 7.5f;

    #pragma unroll
    for (int w = 0; w < NWORDS; w++) {
        int g = w * 32 + lane;
        bool pred = false;
        if (g < n) {
            float4 bb = g_bb[g];
            pred = (bb.y >= tlx) & (bb.x <= thx) & (bb.w >= tly) & (bb.z <= thy);
        }
        unsigned m = __ballot_sync(0xffffffffu, pred);
        if (lane == 0) g_mask[warp][w] = m;
    }
}

// 8x8 tile per block, 64 threads, 1 px/thread, register double-buffered loop.
__global__ __launch_bounds__(64) void gs_render(float* __restrict__ out, int n) {
    __shared__ float4 sA[NMAX + 1];
    __shared__ float4 sB[NMAX + 1];
    __shared__ float  sBV[NMAX + 1];
    __shared__ unsigned short s_idx[NMAX];
    __shared__ int s_cnt;

    const int tid = threadIdx.x;
    const int tile = blockIdx.y * 32 + blockIdx.x;
    const int px0 = blockIdx.x * 8, py0 = blockIdx.y * 8;

    // warp 0: expand bitmask into ordered candidate index list
    if (tid < 32) {
        unsigned word = (tid < NWORDS) ? g_mask[tile][tid] : 0u;
        int c = __popc(word);
        int sc = c;
        #pragma unroll
        for (int o = 1; o < 32; o <<= 1) {
            int v = __shfl_up_sync(0xffffffffu, sc, o);
            if (tid >= o) sc += v;
        }
        if (tid == 31) s_cnt = sc;
        int off = sc - c;
        int base = tid * 32;
        while (word) {
            int b = __ffs(word) - 1;
            s_idx[off++] = (unsigned short)(base + b);
            word &= word - 1;
        }
    }
    __syncthreads();
    const int cnt = s_cnt;

    // stage candidates into shared
    for (int k = tid; k < cnt; k += 64) {
        int g = s_idx[k];
        sA[k]  = g_A[g];
        sB[k]  = g_B[g];
        sBV[k] = g_bv[g];
    }
    __syncthreads();

    const float pxc = px0 + (tid & 7) + 0.5f;
    const float pyc = py0 + (tid >> 3) + 0.5f;

    float T = 1.0f, ar = 0.0f, ag = 0.0f, ab = 0.0f;

    // register double-buffer: load k+1 while compositing k (padded arrays)
    float4 A = sA[0];
    float4 B = sB[0];
    float  bv = sBV[0];
    for (int k = 0; k < cnt; k++) {
        float4 An = sA[k + 1];
        float4 Bn = sB[k + 1];
        float  bvn = sBV[k + 1];
        float dx = pxc - A.x;
        float dy = pyc - A.y;
        float sigma = fmaf(A.z, dx*dx, fmaf(A.w, dy*dy, fmaf(B.x, dx*dy, B.y)));
        if (sigma <= CUT_SIGMA) {
            float al = fminf(0.999f, __expf(-sigma));
            float wt = T * al;
            ar = fmaf(wt, B.z, ar);
            ag = fmaf(wt, B.w, ag);
            ab = fmaf(wt, bv, ab);
            T -= wt;
            if (T < 2e-6f) break;
        }
        A = An; B = Bn; bv = bvn;
    }

    int p = (py0 + (tid >> 3)) * W_ + (px0 + (tid & 7));
    out[3*p + 0] = ar;
    out[3*p + 1] = ag;
    out[3*p + 2] = ab;
}

extern "C" void kernel_launch(void* const* d_in, const int* in_sizes, int n_in,
                              void* d_out, int out_size) {
    const float* means  = (const float*)d_in[1];
    const float* quats  = (const float*)d_in[2];
    const float* scales = (const float*)d_in[3];
    const float* opac   = (const float*)d_in[4];
    const float* rgbs   = (const float*)d_in[5];
    int n = in_sizes[4];
    if (n > NMAX) n = NMAX;

    gs_prep_sort<<<(n * 32 + 255) / 256, 256>>>(means, quats, scales, opac, rgbs, n);
    gs_bin<<<(NTILES * 32 + 255) / 256, 256>>>(n);
    dim3 grid(W_ / 8, H_ / 8), block(64);
    gs_render<<<grid, block>>>((float*)d_out, n);
}

// round 7
// speedup vs baseline: 1.9188x; 1.4995x over previous
#include <cuda_runtime.h>
#include <math.h>

#define W_ 256
#define H_ 256
#define NMAX 768
#define NWORDS 24               // ceil(768/32)
#define NTILES 1024             // 32x32 tiles of 8x8 px
#define CUT_SIGMA 5.5412636f    // log(255): alpha >= 1/255  <=>  sigma <= log(255)

// depth-sorted gaussian data (written at rank)
__device__ float4 g_A[NMAX];    // mx, my, 0.5*conicA, 0.5*conicC
__device__ float4 g_B[NMAX];    // conicB, bias(=-log op), r, g
__device__ float  g_bv[NMAX];   // blue
__device__ unsigned g_mask[NTILES][NWORDS];  // per-tile candidate bitmask (bit = sorted rank)

__global__ void gs_zero_mask() {
    ((unsigned*)g_mask)[blockIdx.x * 1024 + threadIdx.x] = 0u;
}

// Fused preprocess + stable rank sort + tile binning. ONE WARP PER GAUSSIAN.
__global__ __launch_bounds__(256) void gs_prep_sort(
        const float* __restrict__ means,
        const float* __restrict__ quats,
        const float* __restrict__ scales,
        const float* __restrict__ opac_in,
        const float* __restrict__ rgbs,
        int n) {
    const int gw = (blockIdx.x * 256 + threadIdx.x) >> 5;
    const int lane = threadIdx.x & 31;
    if (gw >= n) return;

    // stable ascending rank by z (tz = z + 8 monotone)
    float zi = __ldg(&means[gw*3+2]);
    int rank = 0;
    for (int j = lane; j < n; j += 32) {
        float zj = __ldg(&means[j*3+2]);
        rank += (zj < zi || (zj == zi && j < gw)) ? 1 : 0;
    }
    #pragma unroll
    for (int o = 16; o > 0; o >>= 1)
        rank += __shfl_down_sync(0xffffffffu, rank, o);
    rank = __shfl_sync(0xffffffffu, rank, 0);

    // projection (all lanes redundantly; broadcast loads)
    const int i = gw;
    float qw = __ldg(&quats[i*4+0]), qx = __ldg(&quats[i*4+1]);
    float qy = __ldg(&quats[i*4+2]), qz = __ldg(&quats[i*4+3]);
    float inv = rsqrtf(qw*qw + qx*qx + qy*qy + qz*qz);
    float w = qw*inv, x = qx*inv, y = qy*inv, z = qz*inv;

    float R00 = 1.f - 2.f*(y*y + z*z), R01 = 2.f*(x*y - w*z), R02 = 2.f*(x*z + w*y);
    float R10 = 2.f*(x*y + w*z), R11 = 1.f - 2.f*(x*x + z*z), R12 = 2.f*(y*z - w*x);
    float R20 = 2.f*(x*z - w*y), R21 = 2.f*(y*z + w*x), R22 = 1.f - 2.f*(x*x + y*y);

    float sx = __ldg(&scales[i*3+0]), sy = __ldg(&scales[i*3+1]), szc = __ldg(&scales[i*3+2]);
    float s0 = sx*sx, s1 = sy*sy, s2 = szc*szc;

    float C00 = R00*R00*s0 + R01*R01*s1 + R02*R02*s2;
    float C01 = R00*R10*s0 + R01*R11*s1 + R02*R12*s2;
    float C02 = R00*R20*s0 + R01*R21*s1 + R02*R22*s2;
    float C11 = R10*R10*s0 + R11*R11*s1 + R12*R12*s2;
    float C12 = R10*R20*s0 + R11*R21*s1 + R12*R22*s2;
    float C22 = R20*R20*s0 + R21*R21*s1 + R22*R22*s2;

    float tx = __ldg(&means[i*3+0]), ty = __ldg(&means[i*3+1]), tz = zi + 8.0f;
    const float f = 128.0f;
    float iz = 1.0f / tz;
    float j00 = f * iz;
    float j02 = -f * tx * iz * iz;
    float j12 = -f * ty * iz * iz;

    float a = j00*j00*C00 + 2.f*j00*j02*C02 + j02*j02*C22 + 0.3f;
    float b = j00*j00*C01 + j00*j12*C02 + j02*j00*C12 + j02*j12*C22;
    float c = j00*j00*C11 + 2.f*j00*j12*C12 + j12*j12*C22 + 0.3f;

    float det = a*c - b*b;
    float idet = 1.0f / det;
    float cA = c * idet, cB = -b * idet, cC = a * idet;

    float mx = f * tx * iz + 128.0f;
    float my = f * ty * iz + 128.0f;

    float op = 1.0f / (1.0f + __expf(-__ldg(&opac_in[i])));
    float cr = 1.0f / (1.0f + __expf(-__ldg(&rgbs[i*3+0])));
    float cg = 1.0f / (1.0f + __expf(-__ldg(&rgbs[i*3+1])));
    float cb = 1.0f / (1.0f + __expf(-__ldg(&rgbs[i*3+2])));

    float bias = -__logf(op);
    float tcut = CUT_SIGMA - bias;

    if (lane == 0) {
        g_A[rank]  = make_float4(mx, my, 0.5f * cA, 0.5f * cC);
        g_B[rank]  = make_float4(cB, bias, cr, cg);
        g_bv[rank] = cb;
    }

    // tile binning: bbox from ALPHA_MIN cutoff, scatter bit 'rank' via atomicOr
    if (tcut > 0.0f) {
        float ex = sqrtf(2.0f * tcut * a) + 0.5f;
        float ey = sqrtf(2.0f * tcut * c) + 0.5f;
        // tile tx intersects iff mx-ex <= tx*8+7.5 && mx+ex >= tx*8+0.5
        int tx0 = max(0,  (int)ceilf ((mx - ex - 7.5f) * 0.125f));
        int tx1 = min(31, (int)floorf((mx + ex - 0.5f) * 0.125f));
        int ty0 = max(0,  (int)ceilf ((my - ey - 7.5f) * 0.125f));
        int ty1 = min(31, (int)floorf((my + ey - 0.5f) * 0.125f));
        int nx = tx1 - tx0 + 1, ny = ty1 - ty0 + 1;
        if (nx > 0 && ny > 0) {
            unsigned bit = 1u << (rank & 31);
            int word = rank >> 5;
            int total = nx * ny;
            for (int t = lane; t < total; t += 32) {
                int ttx = tx0 + (t % nx);
                int tty = ty0 + (t / nx);
                atomicOr(&g_mask[tty * 32 + ttx][word], bit);
            }
        }
    }
}

// 8x8 tile per block, 128 threads: threads 0-63 composite the FRONT half of the
// sorted candidate list, threads 64-127 the REAR half (same 64 pixels).
// Combine: out = front_rgb + T_front * rear_rgb  (alpha compositing is associative).
__global__ __launch_bounds__(128) void gs_render(float* __restrict__ out, int n) {
    __shared__ float4 sA[NMAX + 1];
    __shared__ float4 sB[NMAX + 1];
    __shared__ float  sBV[NMAX + 1];
    __shared__ unsigned short s_idx[NMAX];
    __shared__ float cT[64], cR[64], cG[64], cB_[64];
    __shared__ int s_cnt;

    const int tid = threadIdx.x;
    const int tile = blockIdx.y * 32 + blockIdx.x;
    const int px0 = blockIdx.x * 8, py0 = blockIdx.y * 8;

    // warp 0: expand bitmask into ordered candidate index list
    if (tid < 32) {
        unsigned word = (tid < NWORDS) ? g_mask[tile][tid] : 0u;
        int c = __popc(word);
        int sc = c;
        #pragma unroll
        for (int o = 1; o < 32; o <<= 1) {
            int v = __shfl_up_sync(0xffffffffu, sc, o);
            if (tid >= o) sc += v;
        }
        if (tid == 31) s_cnt = sc;
        int off = sc - c;
        int base = tid * 32;
        while (word) {
            int b = __ffs(word) - 1;
            s_idx[off++] = (unsigned short)(base + b);
            word &= word - 1;
        }
    }
    __syncthreads();
    const int cnt = s_cnt;

    // stage candidates into shared (all 128 threads)
    for (int k = tid; k < cnt; k += 128) {
        int g = s_idx[k];
        sA[k]  = g_A[g];
        sB[k]  = g_B[g];
        sBV[k] = g_bv[g];
    }
    __syncthreads();

    const int px  = tid & 63;               // pixel id within tile
    const bool front = (tid < 64);
    const int half = cnt >> 1;
    const int kb = front ? 0 : half;
    const int ke = front ? half : cnt;

    const float pxc = px0 + (px & 7) + 0.5f;
    const float pyc = py0 + (px >> 3) + 0.5f;

    float T = 1.0f, ar = 0.0f, ag = 0.0f, ab = 0.0f;

    float4 A = sA[kb];
    float4 B = sB[kb];
    float  bv = sBV[kb];
    for (int k = kb; k < ke; k++) {
        float4 An = sA[k + 1];
        float4 Bn = sB[k + 1];
        float  bvn = sBV[k + 1];
        float dx = pxc - A.x;
        float dy = pyc - A.y;
        float sigma = fmaf(A.z, dx*dx, fmaf(A.w, dy*dy, fmaf(B.x, dx*dy, B.y)));
        if (sigma <= CUT_SIGMA) {
            float al = fminf(0.999f, __expf(-sigma));
            float wt = T * al;
            ar = fmaf(wt, B.z, ar);
            ag = fmaf(wt, B.w, ag);
            ab = fmaf(wt, bv, ab);
            T -= wt;
            if (T < 2e-6f) break;   // truncation error < 2e-6 absolute (either half)
        }
        A = An; B = Bn; bv = bvn;
    }

    if (!front) {
        cT[px] = T; cR[px] = ar; cG[px] = ag; cB_[px] = ab;
    }
    __syncthreads();

    if (front) {
        ar = fmaf(T, cR[px], ar);
        ag = fmaf(T, cG[px], ag);
        ab = fmaf(T, cB_[px], ab);
        int p = (py0 + (px >> 3)) * W_ + (px0 + (px & 7));
        out[3*p + 0] = ar;
        out[3*p + 1] = ag;
        out[3*p + 2] = ab;
    }
}

extern "C" void kernel_launch(void* const* d_in, const int* in_sizes, int n_in,
                              void* d_out, int out_size) {
    const float* means  = (const float*)d_in[1];
    const float* quats  = (const float*)d_in[2];
    const float* scales = (const float*)d_in[3];
    const float* opac   = (const float*)d_in[4];
    const float* rgbs   = (const float*)d_in[5];
    int n = in_sizes[4];
    if (n > NMAX) n = NMAX;

    gs_zero_mask<<<NTILES * NWORDS / 1024, 1024>>>();
    gs_prep_sort<<<(n * 32 + 255) / 256, 256>>>(means, quats, scales, opac, rgbs, n);
    dim3 grid(W_ / 8, H_ / 8), block(128);
    gs_render<<<grid, block>>>((float*)d_out, n);
}

// round 8
// speedup vs baseline: 2.5139x; 1.3101x over previous
#include <cuda_runtime.h>
#include <math.h>

#define W_ 256
#define H_ 256
#define NMAX 768
#define NWORDS 24               // ceil(768/32)
#define CUT_SIGMA 5.5412636f    // log(255): alpha >= 1/255  <=>  sigma <= log(255)

// depth-sorted gaussian data (written at rank)
__device__ float4 g_A[NMAX];    // mx, my, 0.5*conicA, 0.5*conicC
__device__ float4 g_B[NMAX];    // conicB, bias(=-log op), r, g
__device__ float  g_bv[NMAX];   // blue
__device__ float4 g_bb[NMAX];   // x0, x1, y0, y1

// Fused preprocess + stable rank sort. ONE WARP PER GAUSSIAN.
__global__ __launch_bounds__(256) void gs_prep_sort(
        const float* __restrict__ means,
        const float* __restrict__ quats,
        const float* __restrict__ scales,
        const float* __restrict__ opac_in,
        const float* __restrict__ rgbs,
        int n) {
    const int gw = (blockIdx.x * 256 + threadIdx.x) >> 5;
    const int lane = threadIdx.x & 31;
    if (gw >= n) return;

    // stable ascending rank by z (tz = z + 8 monotone)
    float zi = __ldg(&means[gw*3+2]);
    int rank = 0;
    for (int j = lane; j < n; j += 32) {
        float zj = __ldg(&means[j*3+2]);
        rank += (zj < zi || (zj == zi && j < gw)) ? 1 : 0;
    }
    #pragma unroll
    for (int o = 16; o > 0; o >>= 1)
        rank += __shfl_down_sync(0xffffffffu, rank, o);
    rank = __shfl_sync(0xffffffffu, rank, 0);

    if (lane != 0) return;

    const int i = gw;
    float qw = __ldg(&quats[i*4+0]), qx = __ldg(&quats[i*4+1]);
    float qy = __ldg(&quats[i*4+2]), qz = __ldg(&quats[i*4+3]);
    float inv = rsqrtf(qw*qw + qx*qx + qy*qy + qz*qz);
    float w = qw*inv, x = qx*inv, y = qy*inv, z = qz*inv;

    float R00 = 1.f - 2.f*(y*y + z*z), R01 = 2.f*(x*y - w*z), R02 = 2.f*(x*z + w*y);
    float R10 = 2.f*(x*y + w*z), R11 = 1.f - 2.f*(x*x + z*z), R12 = 2.f*(y*z - w*x);
    float R20 = 2.f*(x*z - w*y), R21 = 2.f*(y*z + w*x), R22 = 1.f - 2.f*(x*x + y*y);

    float sx = __ldg(&scales[i*3+0]), sy = __ldg(&scales[i*3+1]), szc = __ldg(&scales[i*3+2]);
    float s0 = sx*sx, s1 = sy*sy, s2 = szc*szc;

    float C00 = R00*R00*s0 + R01*R01*s1 + R02*R02*s2;
    float C01 = R00*R10*s0 + R01*R11*s1 + R02*R12*s2;
    float C02 = R00*R20*s0 + R01*R21*s1 + R02*R22*s2;
    float C11 = R10*R10*s0 + R11*R11*s1 + R12*R12*s2;
    float C12 = R10*R20*s0 + R11*R21*s1 + R12*R22*s2;
    float C22 = R20*R20*s0 + R21*R21*s1 + R22*R22*s2;

    float tx = __ldg(&means[i*3+0]), ty = __ldg(&means[i*3+1]), tz = zi + 8.0f;
    const float f = 128.0f;
    float iz = 1.0f / tz;
    float j00 = f * iz;
    float j02 = -f * tx * iz * iz;
    float j12 = -f * ty * iz * iz;

    float a = j00*j00*C00 + 2.f*j00*j02*C02 + j02*j02*C22 + 0.3f;
    float b = j00*j00*C01 + j00*j12*C02 + j02*j00*C12 + j02*j12*C22;
    float c = j00*j00*C11 + 2.f*j00*j12*C12 + j12*j12*C22 + 0.3f;

    float det = a*c - b*b;
    float idet = 1.0f / det;
    float cA = c * idet, cB = -b * idet, cC = a * idet;

    float mx = f * tx * iz + 128.0f;
    float my = f * ty * iz + 128.0f;

    float op = 1.0f / (1.0f + __expf(-__ldg(&opac_in[i])));
    float cr = 1.0f / (1.0f + __expf(-__ldg(&rgbs[i*3+0])));
    float cg = 1.0f / (1.0f + __expf(-__ldg(&rgbs[i*3+1])));
    float cb = 1.0f / (1.0f + __expf(-__ldg(&rgbs[i*3+2])));

    float bias = -__logf(op);
    float tcut = CUT_SIGMA - bias;
    float ex, ey;
    if (tcut > 0.0f) {
        ex = sqrtf(2.0f * tcut * a) + 0.5f;
        ey = sqrtf(2.0f * tcut * c) + 0.5f;
    } else {
        ex = -1e30f; ey = -1e30f;   // empty bbox
    }

    g_A[rank]  = make_float4(mx, my, 0.5f * cA, 0.5f * cC);
    g_B[rank]  = make_float4(cB, bias, cr, cg);
    g_bv[rank] = cb;
    g_bb[rank] = make_float4(mx - ex, mx + ex, my - ey, my + ey);
}

// 8x8 tile per block, 256 threads. Inline bitmask binning (8 warps x 3 ballot
// words), then 4-way split of the sorted candidate list across 64-thread
// groups; combine with the alpha-compositing monoid.
__global__ __launch_bounds__(256) void gs_render(float* __restrict__ out, int n) {
    __shared__ float4 sA[NMAX + 1];
    __shared__ float4 sB[NMAX + 1];
    __shared__ float  sBV[NMAX + 1];
    __shared__ unsigned short s_idx[NMAX];
    __shared__ unsigned s_mask[NWORDS];
    __shared__ float cT[3][64], cR[3][64], cG[3][64], cBv[3][64];
    __shared__ int s_cnt;

    const int tid = threadIdx.x;
    const int warp = tid >> 5, lane = tid & 31;
    const int px0 = blockIdx.x * 8, py0 = blockIdx.y * 8;

    const float tlx = px0 + 0.5f, thx = px0 + 7.5f;
    const float tly = py0 + 0.5f, thy = py0 + 7.5f;

    // inline binning: warp w covers words 3w..3w+2 (bit index = sorted rank)
    #pragma unroll
    for (int ww = 0; ww < 3; ww++) {
        int word = warp * 3 + ww;
        int g = word * 32 + lane;
        bool pred = false;
        if (g < n) {
            float4 bb = g_bb[g];
            pred = (bb.y >= tlx) & (bb.x <= thx) & (bb.w >= tly) & (bb.z <= thy);
        }
        unsigned m = __ballot_sync(0xffffffffu, pred);
        if (lane == 0) s_mask[word] = m;
    }
    __syncthreads();

    // warp 0: expand bitmask into ordered candidate index list
    if (tid < 32) {
        unsigned word = (tid < NWORDS) ? s_mask[tid] : 0u;
        int c = __popc(word);
        int sc = c;
        #pragma unroll
        for (int o = 1; o < 32; o <<= 1) {
            int v = __shfl_up_sync(0xffffffffu, sc, o);
            if (tid >= o) sc += v;
        }
        if (tid == 31) s_cnt = sc;
        int off = sc - c;
        int base = tid * 32;
        while (word) {
            int b = __ffs(word) - 1;
            s_idx[off++] = (unsigned short)(base + b);
            word &= word - 1;
        }
    }
    __syncthreads();
    const int cnt = s_cnt;

    // stage candidates into shared
    for (int k = tid; k < cnt; k += 256) {
        int g = s_idx[k];
        sA[k]  = g_A[g];
        sB[k]  = g_B[g];
        sBV[k] = g_bv[g];
    }
    __syncthreads();

    const int seg = tid >> 6;      // 0..3: quarter of the list
    const int px  = tid & 63;      // pixel within tile
    const int kb = (seg * cnt) >> 2;
    const int ke = ((seg + 1) * cnt) >> 2;

    const float pxc = px0 + (px & 7) + 0.5f;
    const float pyc = py0 + (px >> 3) + 0.5f;

    float T = 1.0f, ar = 0.0f, ag = 0.0f, ab = 0.0f;

    float4 A = sA[kb];
    float4 B = sB[kb];
    float  bv = sBV[kb];
    for (int k = kb; k < ke; k++) {
        float4 An = sA[k + 1];
        float4 Bn = sB[k + 1];
        float  bvn = sBV[k + 1];
        float dx = pxc - A.x;
        float dy = pyc - A.y;
        float sigma = fmaf(A.z, dx*dx, fmaf(A.w, dy*dy, fmaf(B.x, dx*dy, B.y)));
        if (sigma <= CUT_SIGMA) {
            float al = fminf(0.999f, __expf(-sigma));
            float wt = T * al;
            ar = fmaf(wt, B.z, ar);
            ag = fmaf(wt, B.w, ag);
            ab = fmaf(wt, bv, ab);
            T -= wt;
            if (T < 2e-6f) break;   // truncation error < 2e-6 absolute
        }
        A = An; B = Bn; bv = bvn;
    }

    if (seg > 0) {
        cT[seg-1][px] = T;
        cR[seg-1][px] = ar;
        cG[seg-1][px] = ag;
        cBv[seg-1][px] = ab;
    }
    __syncthreads();

    if (seg == 0) {
        // out = r0 + T0*(r1 + T1*(r2 + T2*r3))
        float T1 = cT[0][px], T2 = cT[1][px];
        float r = fmaf(T2, cR[2][px], cR[1][px]);
        float g = fmaf(T2, cG[2][px], cG[1][px]);
        float b = fmaf(T2, cBv[2][px], cBv[1][px]);
        r = fmaf(T1, r, cR[0][px]);
        g = fmaf(T1, g, cG[0][px]);
        b = fmaf(T1, b, cBv[0][px]);
        r = fmaf(T, r, ar);
        g = fmaf(T, g, ag);
        b = fmaf(T, b, ab);
        int p = (py0 + (px >> 3)) * W_ + (px0 + (px & 7));
        out[3*p + 0] = r;
        out[3*p + 1] = g;
        out[3*p + 2] = b;
    }
}

extern "C" void kernel_launch(void* const* d_in, const int* in_sizes, int n_in,
                              void* d_out, int out_size) {
    const float* means  = (const float*)d_in[1];
    const float* quats  = (const float*)d_in[2];
    const float* scales = (const float*)d_in[3];
    const float* opac   = (const float*)d_in[4];
    const float* rgbs   = (const float*)d_in[5];
    int n = in_sizes[4];
    if (n > NMAX) n = NMAX;

    gs_prep_sort<<<(n * 32 + 255) / 256, 256>>>(means, quats, scales, opac, rgbs, n);
    dim3 grid(W_ / 8, H_ / 8), block(256);
    gs_render<<<grid, block>>>((float*)d_out, n);
}

// round 9
// speedup vs baseline: 2.7280x; 1.0852x over previous
#include <cuda_runtime.h>
#include <math.h>

#define W_ 256
#define H_ 256
#define NMAX 768
#define NWORDS 24               // ceil(768/32)
#define CUT_SIGMA 5.5412636f    // log(255): alpha >= 1/255  <=>  sigma <= log(255)

// depth-sorted gaussian data (written at rank)
__device__ float4 g_A[NMAX];    // mx, my, 0.5*conicA, 0.5*conicC
__device__ float4 g_B[NMAX];    // conicB, bias(=-log op), r, g
__device__ float  g_bv[NMAX];   // blue
__device__ float4 g_bb[NMAX];   // x0, x1, y0, y1

// Fused preprocess + stable rank sort. ONE WARP PER GAUSSIAN; z staged in smem.
__global__ __launch_bounds__(256) void gs_prep_sort(
        const float* __restrict__ means,
        const float* __restrict__ quats,
        const float* __restrict__ scales,
        const float* __restrict__ opac_in,
        const float* __restrict__ rgbs,
        int n) {
    __shared__ float s_z[NMAX];
    const int tid = threadIdx.x;
    const int gw = (blockIdx.x * 256 + tid) >> 5;
    const int lane = tid & 31;

    for (int j = tid; j < n; j += 256)
        s_z[j] = __ldg(&means[j*3+2]);
    __syncthreads();

    if (gw >= n) return;

    // stable ascending rank by z (tz = z + 8 monotone)
    float zi = s_z[gw];
    int rank = 0;
    for (int j = lane; j < n; j += 32) {
        float zj = s_z[j];
        rank += (zj < zi || (zj == zi && j < gw)) ? 1 : 0;
    }
    #pragma unroll
    for (int o = 16; o > 0; o >>= 1)
        rank += __shfl_down_sync(0xffffffffu, rank, o);

    if (lane != 0) return;

    const int i = gw;
    float qw = __ldg(&quats[i*4+0]), qx = __ldg(&quats[i*4+1]);
    float qy = __ldg(&quats[i*4+2]), qz = __ldg(&quats[i*4+3]);
    float inv = rsqrtf(qw*qw + qx*qx + qy*qy + qz*qz);
    float w = qw*inv, x = qx*inv, y = qy*inv, z = qz*inv;

    float R00 = 1.f - 2.f*(y*y + z*z), R01 = 2.f*(x*y - w*z), R02 = 2.f*(x*z + w*y);
    float R10 = 2.f*(x*y + w*z), R11 = 1.f - 2.f*(x*x + z*z), R12 = 2.f*(y*z - w*x);
    float R20 = 2.f*(x*z - w*y), R21 = 2.f*(y*z + w*x), R22 = 1.f - 2.f*(x*x + y*y);

    float sx = __ldg(&scales[i*3+0]), sy = __ldg(&scales[i*3+1]), szc = __ldg(&scales[i*3+2]);
    float s0 = sx*sx, s1 = sy*sy, s2 = szc*szc;

    float C00 = R00*R00*s0 + R01*R01*s1 + R02*R02*s2;
    float C01 = R00*R10*s0 + R01*R11*s1 + R02*R12*s2;
    float C02 = R00*R20*s0 + R01*R21*s1 + R02*R22*s2;
    float C11 = R10*R10*s0 + R11*R11*s1 + R12*R12*s2;
    float C12 = R10*R20*s0 + R11*R21*s1 + R12*R22*s2;
    float C22 = R20*R20*s0 + R21*R21*s1 + R22*R22*s2;

    float tx = __ldg(&means[i*3+0]), ty = __ldg(&means[i*3+1]), tz = zi + 8.0f;
    const float f = 128.0f;
    float iz = 1.0f / tz;
    float j00 = f * iz;
    float j02 = -f * tx * iz * iz;
    float j12 = -f * ty * iz * iz;

    float a = j00*j00*C00 + 2.f*j00*j02*C02 + j02*j02*C22 + 0.3f;
    float b = j00*j00*C01 + j00*j12*C02 + j02*j00*C12 + j02*j12*C22;
    float c = j00*j00*C11 + 2.f*j00*j12*C12 + j12*j12*C22 + 0.3f;

    float det = a*c - b*b;
    float idet = 1.0f / det;
    float cA = c * idet, cB = -b * idet, cC = a * idet;

    float mx = f * tx * iz + 128.0f;
    float my = f * ty * iz + 128.0f;

    float op = 1.0f / (1.0f + __expf(-__ldg(&opac_in[i])));
    float cr = 1.0f / (1.0f + __expf(-__ldg(&rgbs[i*3+0])));
    float cg = 1.0f / (1.0f + __expf(-__ldg(&rgbs[i*3+1])));
    float cb = 1.0f / (1.0f + __expf(-__ldg(&rgbs[i*3+2])));

    float bias = -__logf(op);
    float tcut = CUT_SIGMA - bias;
    float ex, ey;
    if (tcut > 0.0f) {
        ex = sqrtf(2.0f * tcut * a) + 0.5f;
        ey = sqrtf(2.0f * tcut * c) + 0.5f;
    } else {
        ex = -1e30f; ey = -1e30f;   // empty bbox
    }

    g_A[rank]  = make_float4(mx, my, 0.5f * cA, 0.5f * cC);
    g_B[rank]  = make_float4(cB, bias, cr, cg);
    g_bv[rank] = cb;
    g_bb[rank] = make_float4(mx - ex, mx + ex, my - ey, my + ey);
}

// 8x8 tile per block, 256 threads. Inline ballot binning, fully parallel
// expand+stage (every lane writes its own slot), 4-way list split with
// alpha-compositing monoid combine.
__global__ __launch_bounds__(256) void gs_render(float* __restrict__ out, int n) {
    __shared__ float4 sA[NMAX + 1];
    __shared__ float4 sB[NMAX + 1];
    __shared__ float  sBV[NMAX + 1];
    __shared__ unsigned s_mask[NWORDS];
    __shared__ float cT[3][64], cR[3][64], cG[3][64], cBv[3][64];

    const int tid = threadIdx.x;
    const int warp = tid >> 5, lane = tid & 31;
    const int px0 = blockIdx.x * 8, py0 = blockIdx.y * 8;

    const float tlx = px0 + 0.5f, thx = px0 + 7.5f;
    const float tly = py0 + 0.5f, thy = py0 + 7.5f;

    // ballot binning: warp w covers words 3w..3w+2 (bit index = sorted rank)
    unsigned myms[3];
    bool mypred[3];
    #pragma unroll
    for (int ww = 0; ww < 3; ww++) {
        int word = warp * 3 + ww;
        int g = word * 32 + lane;
        bool pred = false;
        if (g < n) {
            float4 bb = g_bb[g];
            pred = (bb.y >= tlx) & (bb.x <= thx) & (bb.w >= tly) & (bb.z <= thy);
        }
        unsigned m = __ballot_sync(0xffffffffu, pred);
        myms[ww] = m;
        mypred[ww] = pred;
        if (lane == 0) s_mask[word] = m;
    }
    __syncthreads();

    // every warp redundantly computes the 24-word popc prefix (lane-parallel)
    unsigned wm = (lane < NWORDS) ? s_mask[lane] : 0u;
    int pc = __popc(wm);
    int sc = pc;
    #pragma unroll
    for (int o = 1; o < 32; o <<= 1) {
        int v = __shfl_up_sync(0xffffffffu, sc, o);
        if (lane >= o) sc += v;
    }
    const int cnt = __shfl_sync(0xffffffffu, sc, NWORDS - 1);
    const int excl = sc - pc;   // exclusive prefix for word == lane

    // fused expand + stage: each lane writes its own candidate directly
    #pragma unroll
    for (int ww = 0; ww < 3; ww++) {
        int word = warp * 3 + ww;
        unsigned m = myms[ww];
        int base = __shfl_sync(0xffffffffu, excl, word);
        if (mypred[ww]) {
            int pos = base + __popc(m & ((1u << lane) - 1u));
            int g = word * 32 + lane;
            sA[pos]  = g_A[g];
            sB[pos]  = g_B[g];
            sBV[pos] = g_bv[g];
        }
    }
    __syncthreads();

    const int seg = tid >> 6;      // 0..3: quarter of the sorted candidate list
    const int px  = tid & 63;      // pixel within tile
    const int kb = (seg * cnt) >> 2;
    const int ke = ((seg + 1) * cnt) >> 2;

    const float pxc = px0 + (px & 7) + 0.5f;
    const float pyc = py0 + (px >> 3) + 0.5f;

    float T = 1.0f, ar = 0.0f, ag = 0.0f, ab = 0.0f;

    float4 A = sA[kb];
    float4 B = sB[kb];
    float  bv = sBV[kb];
    for (int k = kb; k < ke; k++) {
        float4 An = sA[k + 1];
        float4 Bn = sB[k + 1];
        float  bvn = sBV[k + 1];
        float dx = pxc - A.x;
        float dy = pyc - A.y;
        float sigma = fmaf(A.z, dx*dx, fmaf(A.w, dy*dy, fmaf(B.x, dx*dy, B.y)));
        if (sigma <= CUT_SIGMA) {
            float al = fminf(0.999f, __expf(-sigma));
            float wt = T * al;
            ar = fmaf(wt, B.z, ar);
            ag = fmaf(wt, B.w, ag);
            ab = fmaf(wt, bv, ab);
            T -= wt;
            if (T < 2e-6f) break;   // truncation error < 2e-6 absolute
        }
        A = An; B = Bn; bv = bvn;
    }

    if (seg > 0) {
        cT[seg-1][px] = T;
        cR[seg-1][px] = ar;
        cG[seg-1][px] = ag;
        cBv[seg-1][px] = ab;
    }
    __syncthreads();

    if (seg == 0) {
        // out = r0 + T0*(r1 + T1*(r2 + T2*r3))
        float T1 = cT[0][px], T2 = cT[1][px];
        float r = fmaf(T2, cR[2][px], cR[1][px]);
        float g = fmaf(T2, cG[2][px], cG[1][px]);
        float b = fmaf(T2, cBv[2][px], cBv[1][px]);
        r = fmaf(T1, r, cR[0][px]);
        g = fmaf(T1, g, cG[0][px]);
        b = fmaf(T1, b, cBv[0][px]);
        r = fmaf(T, r, ar);
        g = fmaf(T, g, ag);
        b = fmaf(T, b, ab);
        int p = (py0 + (px >> 3)) * W_ + (px0 + (px & 7));
        out[3*p + 0] = r;
        out[3*p + 1] = g;
        out[3*p + 2] = b;
    }
}

extern "C" void kernel_launch(void* const* d_in, const int* in_sizes, int n_in,
                              void* d_out, int out_size) {
    const float* means  = (const float*)d_in[1];
    const float* quats  = (const float*)d_in[2];
    const float* scales = (const float*)d_in[3];
    const float* opac   = (const float*)d_in[4];
    const float* rgbs   = (const float*)d_in[5];
    int n = in_sizes[4];
    if (n > NMAX) n = NMAX;

    gs_prep_sort<<<(n * 32 + 255) / 256, 256>>>(means, quats, scales, opac, rgbs, n);
    dim3 grid(W_ / 8, H_ / 8), block(256);
    gs_render<<<grid, block>>>((float*)d_out, n);
}